// round 1
// baseline (speedup 1.0000x reference)
#include <cuda_runtime.h>

#define BB 8
#define CC 32
#define HH 384
#define WW 768
#define NPIX (BB * HH * WW)          // 2359296
#define CHW  ((size_t)CC * HH * WW)
#define HW   ((size_t)HH * WW)

__global__ __launch_bounds__(256)
void disparity_warp_kernel(const float* __restrict__ src,
                           const float* __restrict__ disp,
                           float* __restrict__ out) {
    int idx = blockIdx.x * 256 + threadIdx.x;
    if (idx >= NPIX) return;

    int w = idx % WW;
    int t = idx / WW;
    int h = t % HH;
    int b = t / HH;

    float d = disp[idx];
    float ix = ((float)w - d) * (768.0f / 767.0f) - 0.5f;
    float iy = (float)h * (384.0f / 383.0f) - 0.5f;

    float x0f = floorf(ix);
    float y0f = floorf(iy);
    float fx = ix - x0f;
    float fy = iy - y0f;
    int x0 = (int)x0f, y0 = (int)y0f;
    int x1 = x0 + 1,  y1 = y0 + 1;

    // zero-padding: fold OOB mask into weights, clamp indices for the load
    bool xi0 = (x0 >= 0) & (x0 < WW);
    bool xi1 = (x1 >= 0) & (x1 < WW);
    bool yi0 = (y0 >= 0) & (y0 < HH);
    bool yi1 = (y1 >= 0) & (y1 < HH);

    float w00 = (1.0f - fy) * (1.0f - fx) * (float)(xi0 & yi0);
    float w01 = (1.0f - fy) * fx          * (float)(xi1 & yi0);
    float w10 = fy * (1.0f - fx)          * (float)(xi0 & yi1);
    float w11 = fy * fx                   * (float)(xi1 & yi1);

    int cx0 = min(max(x0, 0), WW - 1);
    int cx1 = min(max(x1, 0), WW - 1);
    int cy0 = min(max(y0, 0), HH - 1);
    int cy1 = min(max(y1, 0), HH - 1);

    int o00 = cy0 * WW + cx0;
    int o01 = cy0 * WW + cx1;
    int o10 = cy1 * WW + cx0;
    int o11 = cy1 * WW + cx1;

    const float* sb = src + (size_t)b * CHW;
    float* ob = out + (size_t)b * CHW + (size_t)h * WW + w;

    #pragma unroll 8
    for (int c = 0; c < CC; ++c) {
        const float* p = sb + (size_t)c * HW;
        float v = p[o00] * w00 + p[o01] * w01 + p[o10] * w10 + p[o11] * w11;
        ob[(size_t)c * HW] = v;
    }
}

extern "C" void kernel_launch(void* const* d_in, const int* in_sizes, int n_in,
                              void* d_out, int out_size) {
    const float* src  = (const float*)d_in[0];
    const float* disp = (const float*)d_in[1];
    float* out = (float*)d_out;

    int blocks = (NPIX + 255) / 256;   // 9216 exactly
    disparity_warp_kernel<<<blocks, 256>>>(src, disp, out);
}